// round 1
// baseline (speedup 1.0000x reference)
#include <cuda_runtime.h>
#include <cstdint>

#define B_ 32
#define I_ 1152
#define O_ 10
#define D_ 16
#define H_ 10
#define S_ 922

// Scratch (no allocations allowed): layouts are [B,O,I] for coalesced access
__device__ float    g_vn  [B_ * O_ * I_];   // ||u[b,i,o,:]||
__device__ unsigned g_mask[B_ * O_ * I_];   // bit h set if i in hypothesis h sample
__device__ int      g_is64;

// ---------------------------------------------------------------------------
// Detect whether sample_idx is int64 or int32. Values are in [0,1152), so if
// the buffer is int64, every odd 32-bit word is exactly 0. If int32, the odd
// words are index values (overwhelmingly nonzero over 2048 samples).
// ---------------------------------------------------------------------------
__global__ void detect_kernel(const unsigned* __restrict__ idx32) {
    __shared__ unsigned red[256];
    unsigned v = 0;
    for (int t = threadIdx.x; t < 2048; t += 256) v |= idx32[2 * t + 1];
    red[threadIdx.x] = v;
    __syncthreads();
    for (int s = 128; s > 0; s >>= 1) {
        if (threadIdx.x < (unsigned)s) red[threadIdx.x] |= red[threadIdx.x + s];
        __syncthreads();
    }
    if (threadIdx.x == 0) g_is64 = (red[0] == 0u) ? 1 : 0;
}

// ---------------------------------------------------------------------------
// Zero the hypothesis bitmask (must be re-zeroed every launch: graph replays)
// ---------------------------------------------------------------------------
__global__ void zero_kernel() {
    int t = blockIdx.x * blockDim.x + threadIdx.x;
    if (t < B_ * O_ * I_) g_mask[t] = 0u;
}

// ---------------------------------------------------------------------------
// Per-(b,i,o) L2 norm of u over d. Thread id: i fastest -> coalesced store.
// ---------------------------------------------------------------------------
__global__ void norm_kernel(const float* __restrict__ u) {
    int t = blockIdx.x * blockDim.x + threadIdx.x;
    if (t >= B_ * O_ * I_) return;
    int i = t % I_;
    int r = t / I_;
    int o = r % O_;
    int b = r / O_;
    const float4* p = (const float4*)(u + ((size_t)(b * I_ + i) * O_ + o) * D_);
    float4 q0 = p[0], q1 = p[1], q2 = p[2], q3 = p[3];
    float s = q0.x * q0.x + q0.y * q0.y + q0.z * q0.z + q0.w * q0.w
            + q1.x * q1.x + q1.y * q1.y + q1.z * q1.z + q1.w * q1.w
            + q2.x * q2.x + q2.y * q2.y + q2.z * q2.z + q2.w * q2.w
            + q3.x * q3.x + q3.y * q3.y + q3.z * q3.z + q3.w * q3.w;
    g_vn[(b * O_ + o) * I_ + i] = sqrtf(s);
}

// ---------------------------------------------------------------------------
// Scatter sample_idx into the bitmask. One thread per (b,s,o,h) element.
// ---------------------------------------------------------------------------
__global__ void scatter_kernel(const int* __restrict__ idx32) {
    int t = blockIdx.x * blockDim.x + threadIdx.x;
    if (t >= B_ * S_ * O_ * H_) return;
    int i = g_is64 ? idx32[2 * t] : idx32[t];
    int h = t % H_;
    int r = t / H_;
    int o = r % O_;
    r /= O_;            // r = b*S + s
    int b = r / S_;
    atomicOr(&g_mask[(b * O_ + o) * I_ + i], 1u << h);
}

// ---------------------------------------------------------------------------
// Main routing kernel: one block per (b,o). 128 threads.
// Pass 1: Mu[h][d] via masked weighted mean (16-lane groups own one d each).
// Pass 2: loss[h] = sum_i sqrt(||u_i||^2 - 2 u_i.Mu_h + ||Mu_h||^2); argmin;
// emit Mu[h*].
// ---------------------------------------------------------------------------
__global__ void __launch_bounds__(128) route_kernel(const float* __restrict__ u,
                                                    float* __restrict__ out) {
    const int bo  = blockIdx.x;           // 0..B*O-1
    const int b   = bo / O_;
    const int o   = bo % O_;
    const int tid = threadIdx.x;
    const int g   = tid >> 4;             // group 0..7
    const int d   = tid & 15;             // dim owned by this lane

    const float*    vn = g_vn   + (size_t)bo * I_;
    const unsigned* mk = g_mask + (size_t)bo * I_;
    const float*    ub = u + ((size_t)b * I_ * O_ + o) * D_;  // ub[i*O*D + d]

    // ---- Pass 1: masked accumulation ----
    float acc[H_], den[H_];
#pragma unroll
    for (int h = 0; h < H_; h++) { acc[h] = 0.f; den[h] = 0.f; }

#pragma unroll 2
    for (int i = g; i < I_; i += 8) {
        unsigned m  = mk[i];
        float    v  = vn[i];
        float    ud = ub[(size_t)i * (O_ * D_) + d];
        float    t0 = v * ud;
#pragma unroll
        for (int h = 0; h < H_; h++) {
            if (m & (1u << h)) { acc[h] += t0; den[h] += v; }
        }
    }

    __shared__ float s_num[8][H_][16];
    __shared__ float s_den[8][H_];
#pragma unroll
    for (int h = 0; h < H_; h++) s_num[g][h][d] = acc[h];
    if (d == 0) {
#pragma unroll
        for (int h = 0; h < H_; h++) s_den[g][h] = den[h];
    }
    __syncthreads();

    __shared__ float s_Mu[H_][16];
    __shared__ float s_mu2[H_];
    for (int idx = tid; idx < H_ * 16; idx += 128) {
        int h  = idx >> 4;
        int dd = idx & 15;
        float sn = 0.f, dn = 0.f;
#pragma unroll
        for (int gg = 0; gg < 8; gg++) { sn += s_num[gg][h][dd]; dn += s_den[gg][h]; }
        s_Mu[h][dd] = sn / dn;
    }
    __syncthreads();
    if (tid < H_) {
        float m2 = 0.f;
#pragma unroll
        for (int dd = 0; dd < 16; dd++) { float x = s_Mu[tid][dd]; m2 += x * x; }
        s_mu2[tid] = m2;
    }
    __syncthreads();

    // ---- Pass 2: losses (all i, all h) ----
    float loss[H_];
#pragma unroll
    for (int h = 0; h < H_; h++) loss[h] = 0.f;

    for (int i = tid; i < I_; i += 128) {   // 1152 = 9*128 exactly
        const float4* p = (const float4*)(ub + (size_t)i * (O_ * D_));
        float4 q0 = p[0], q1 = p[1], q2 = p[2], q3 = p[3];
        float v  = vn[i];
        float sq = v * v;
#pragma unroll
        for (int h = 0; h < H_; h++) {
            const float4* mp = (const float4*)&s_Mu[h][0];
            float4 m0 = mp[0], m1 = mp[1], m2 = mp[2], m3 = mp[3];
            float dot = q0.x * m0.x + q0.y * m0.y + q0.z * m0.z + q0.w * m0.w
                      + q1.x * m1.x + q1.y * m1.y + q1.z * m1.z + q1.w * m1.w
                      + q2.x * m2.x + q2.y * m2.y + q2.z * m2.z + q2.w * m2.w
                      + q3.x * m3.x + q3.y * m3.y + q3.z * m3.z + q3.w * m3.w;
            float val = sq + fmaf(-2.f, dot, s_mu2[h]);
            loss[h] += sqrtf(fmaxf(val, 0.f));
        }
    }

    // warp reduce then cross-warp via smem
#pragma unroll
    for (int h = 0; h < H_; h++) {
#pragma unroll
        for (int off = 16; off > 0; off >>= 1)
            loss[h] += __shfl_down_sync(0xffffffffu, loss[h], off);
    }
    __shared__ float s_loss[4][H_];
    int wid = tid >> 5, lane = tid & 31;
    if (lane == 0) {
#pragma unroll
        for (int h = 0; h < H_; h++) s_loss[wid][h] = loss[h];
    }
    __syncthreads();

    __shared__ int s_best;
    if (tid == 0) {
        float bestv = 3.4e38f;
        int   besth = 0;
#pragma unroll
        for (int h = 0; h < H_; h++) {
            float l = s_loss[0][h] + s_loss[1][h] + s_loss[2][h] + s_loss[3][h];
            if (l < bestv) { bestv = l; besth = h; }
        }
        s_best = besth;
    }
    __syncthreads();

    if (tid < D_) out[(size_t)bo * D_ + tid] = s_Mu[s_best][tid];
}

// ---------------------------------------------------------------------------
extern "C" void kernel_launch(void* const* d_in, const int* in_sizes, int n_in,
                              void* d_out, int out_size) {
    const float* u   = (const float*)d_in[0];
    const void*  idx = d_in[1];
    float*       out = (float*)d_out;
    (void)in_sizes; (void)n_in; (void)out_size;

    detect_kernel<<<1, 256>>>((const unsigned*)idx);

    const int nBOI = B_ * O_ * I_;
    zero_kernel<<<(nBOI + 255) / 256, 256>>>();
    norm_kernel<<<(nBOI + 255) / 256, 256>>>(u);

    const int nScatter = B_ * S_ * O_ * H_;
    scatter_kernel<<<(nScatter + 255) / 256, 256>>>((const int*)idx);

    route_kernel<<<B_ * O_, 128>>>(u, out);
}